// round 11
// baseline (speedup 1.0000x reference)
#include <cuda_runtime.h>
#include <math.h>

typedef unsigned long long ull;

#define Bsz 64
#define Tsz 512
#define Esz 256
#define Hsz 512
#define Vsz 128
#define Msz (Bsz*Tsz)   // 32768 rows

// ---------------- scratch (static device arrays; no runtime allocation) -------------
__device__ float g_xw[Msz*Hsz];     // input projection for current layer (t,b,h)
__device__ float g_hs0[Msz*Hsz];    // layer0 hidden states (t,b,h)
__device__ float g_hs1[Msz*Hsz];    // layer1 hidden states (t,b,h)

// ---------------- f32x2 helpers ------------------------------------------------------
__device__ __forceinline__ ull fma2(ull a, ull b, ull c){
    ull d; asm("fma.rn.f32x2 %0, %1, %2, %3;" : "=l"(d) : "l"(a), "l"(b), "l"(c)); return d;
}
__device__ __forceinline__ ull pack2(float x){
    ull d; asm("mov.b64 %0, {%1, %1};" : "=l"(d) : "f"(x)); return d;
}
__device__ __forceinline__ void unpack2(ull v, float& lo, float& hi){
    asm("mov.b64 {%0, %1}, %2;" : "=f"(lo), "=f"(hi) : "l"(v));
}

// branch-free tanh: 1 - 2/(e^{2x}+1). MUFU-based, ~5 instr, rel err ~3e-7.
__device__ __forceinline__ float ftanh(float x){
    float e = __expf(2.0f*x);
    return 1.0f - __fdividef(2.0f, e + 1.0f);
}

// ---------------- cluster helpers ----------------------------------------------------
__device__ __forceinline__ unsigned smem_u32(const void* p){
    unsigned a;
    asm("{ .reg .u64 t; cvta.to.shared.u64 t, %1; cvt.u32.u64 %0, t; }" : "=r"(a) : "l"(p));
    return a;
}
__device__ __forceinline__ unsigned mapa_rank(unsigned laddr, unsigned r){
    unsigned ra; asm("mapa.shared::cluster.u32 %0, %1, %2;" : "=r"(ra) : "r"(laddr), "r"(r));
    return ra;
}
__device__ __forceinline__ void cluster_arrive(){
    asm volatile("barrier.cluster.arrive.aligned;" ::: "memory");
}
__device__ __forceinline__ void cluster_wait(){
    asm volatile("barrier.cluster.wait.aligned;"   ::: "memory");
}
__device__ __forceinline__ void mbar_init(unsigned addr, unsigned cnt){
    asm volatile("mbarrier.init.shared.b64 [%0], %1;" :: "r"(addr), "r"(cnt) : "memory");
}
// arm: arrive (count 1) + expect tx bytes for the current phase of own mbar
__device__ __forceinline__ void mbar_expect(unsigned addr, unsigned txb){
    asm volatile("mbarrier.arrive.expect_tx.shared.b64 _, [%0], %1;"
                 :: "r"(addr), "r"(txb) : "memory");
}
// self-signaling remote store: data + tx-completion both to the SAME remote CTA
__device__ __forceinline__ void st_async(unsigned raddr, float v, unsigned rmbar){
    asm volatile("st.async.shared::cluster.mbarrier::complete_tx::bytes.u32 [%0], %1, [%2];"
                 :: "r"(raddr), "r"(__float_as_uint(v)), "r"(rmbar) : "memory");
}
// wait own mbar phase with cluster-scope acquire (orders inbound async stores)
__device__ __forceinline__ void mbar_wait(unsigned addr, unsigned parity){
    asm volatile("{\n\t.reg .pred P;\n\t"
        "W_%=:\n\t"
        "mbarrier.try_wait.parity.acquire.cluster.shared::cta.b64 P, [%0], %1, 0x989680;\n\t"
        "@!P bra W_%=;\n\t}\n"
        :: "r"(addr), "r"(parity) : "memory");
}

// ---------------- kernel: fp32 GEMM  C[M,N] = A[M,K] @ W[N,K]^T + bias --------------
// mode 0: C row-major by A-row.
// mode 1: A-row=(t*B+b) remapped to out[(b*T+t)*N+n] (logits)
// mode 2: A-row gathered through embedding: A[m][k] = emb[x[b*T+t]][k]  (K=Esz)
__global__ void __launch_bounds__(256) k_gemm(const float* __restrict__ A,
                                              const float* __restrict__ W,
                                              const float* __restrict__ bias,
                                              float* __restrict__ C,
                                              int M, int N, int K, int mode,
                                              const int* __restrict__ xidx){
    __shared__ __align__(16) float As[128*20];   // [m][k], row stride 20 (pad)
    __shared__ __align__(16) float Bs[16*130];   // [k][n], row stride 130 (pad)
    const int tid = threadIdx.x;
    const int m0 = blockIdx.x*128;
    const int n0 = blockIdx.y*128;
    const int tx = tid & 15;       // n-group (8 n each)
    const int ty = tid >> 4;       // m-group (8 m each)
    const int mlA = tid >> 2, qA = tid & 3;
    const int nnB = tid & 127, hfB = tid >> 7;

    ull acc[8][4];
#pragma unroll
    for (int i=0;i<8;i++)
#pragma unroll
        for (int j=0;j<4;j++) acc[i][j] = 0ull;

    for (int k0=0;k0<K;k0+=16){
        __syncthreads();
        // A tile: 128x16
#pragma unroll
        for (int p=0;p<2;p++){
            int m = mlA + p*64;
            int row = m0 + m;
            const float* ap;
            if (mode == 2){
                int b = row & 63; int tt = row >> 6;
                int v = xidx[b*Tsz + tt];
                ap = &A[(size_t)v*Esz + k0 + qA*4];
            } else {
                ap = &A[(size_t)row*K + k0 + qA*4];
            }
            float4 va = *(const float4*)ap;
            *(float4*)&As[m*20 + qA*4] = va;
        }
        // B tile: W[n][k] -> Bs[k][n]
        {
            const float* wp = &W[(size_t)(n0+nnB)*K + k0 + hfB*8];
            float4 v0 = *(const float4*)wp;
            float4 v1 = *(const float4*)(wp+4);
            int kb = hfB*8;
            Bs[(kb+0)*130+nnB]=v0.x; Bs[(kb+1)*130+nnB]=v0.y;
            Bs[(kb+2)*130+nnB]=v0.z; Bs[(kb+3)*130+nnB]=v0.w;
            Bs[(kb+4)*130+nnB]=v1.x; Bs[(kb+5)*130+nnB]=v1.y;
            Bs[(kb+6)*130+nnB]=v1.z; Bs[(kb+7)*130+nnB]=v1.w;
        }
        __syncthreads();
#pragma unroll
        for (int kk=0;kk<16;kk++){
            int k = (kk + tx) & 15;                 // per-lane k rotation: kills bank conflicts
            const ull* bp = (const ull*)&Bs[k*130 + tx*8];
            ull b0=bp[0], b1=bp[1], b2v=bp[2], b3=bp[3];
#pragma unroll
            for (int i=0;i<8;i++){
                ull a2 = pack2(As[(ty*8+i)*20 + k]);
                acc[i][0] = fma2(a2, b0,  acc[i][0]);
                acc[i][1] = fma2(a2, b1,  acc[i][1]);
                acc[i][2] = fma2(a2, b2v, acc[i][2]);
                acc[i][3] = fma2(a2, b3,  acc[i][3]);
            }
        }
    }
    // epilogue: + bias, write (with optional logits remap)
#pragma unroll
    for (int i=0;i<8;i++){
        int row = m0 + ty*8 + i;
        size_t obase;
        if (mode == 1){ int b = row & 63; int tt = row >> 6; obase = ((size_t)b*Tsz + tt)*(size_t)N; }
        else obase = (size_t)row * (size_t)N;
#pragma unroll
        for (int jn=0;jn<4;jn++){
            int n = n0 + tx*8 + jn*2;
            float2 bv = *(const float2*)&bias[n];
            float lo, hi; unpack2(acc[i][jn], lo, hi);
            float2 o; o.x = lo + bv.x; o.y = hi + bv.y;
            *(float2*)&C[obase + n] = o;
        }
    }
}

// ---------------- kernel: FOUR-stream st.async recurrence ----------------------------
// 128 CTAs = 16 clusters x 8 CTAs, 256 thr. Cluster cl owns batches [cl*4, cl*4+4):
// stream s handles batch cl*4+s (4 independent chains sharing the SAME weight regs).
// Between push(stream s, h[t]) and wait(stream s, h[t] at t+1) sit 3 full segments
// of other-stream compute (~1500 cyc) -> st.async flight fully hidden.
// Thread tile per stream: jn=4 j x bn=1 b x kn=32 k = 64 fma2. Weights w2[4][16] ull.
// Reduce: bits 8,4 pure reduction (4+4 shuffles), select-folds bits 2,1 (3 shuffles)
// -> output j0+(kq&3) replicated in all 4 quads; quad q pushes to ranks {2q, 2q+1}.
// Sync: per-(stream,slot) tx-mbarrier, TXB=2048 (8 producers x 64 floats). Protocol
// (arm/parity/guards) identical to the proven R10 kernel. t=511 pushes nothing.
#define CH    36                   // 32 floats + 4 pad per k-slice
#define HB1   (16*CH)              // 16 slices = 576 floats per region
#define HB1B  (HB1*4)              // bytes per region
#define TXB1  2048u                // inbound bytes per region phase: 512 floats

__global__ void __launch_bounds__(256,1) __cluster_dims__(8,1,1)
k_rnn(const float* __restrict__ xw, float* __restrict__ hs,
      const float* __restrict__ Whh, float* __restrict__ hlast){
    __shared__ __align__(16) float sh[8*HB1];            // region = stream*2 + slot
    __shared__ __align__(8) ull mb[8];                   // mbar per region
    const int cl   = blockIdx.x >> 3;
    const int rank = blockIdx.x & 7;
    const int tid  = threadIdx.x;
    const int w    = tid >> 5;
    const int lane = tid & 31;
    const int jq   = lane >> 4;
    const int kq   = lane & 15;
    const int j0   = rank*64 + w*8 + jq*4;
    const int j_out= j0 + (kq & 3);
    const int rq   = kq >> 2;                // quad id -> fanout ranks {2rq, 2rq+1}
    const bool st0 = (rq == 0);              // this quad does the global stores
    const int BH   = Bsz*Hsz;

    // ---- weights: W_hh[j0+jj][kq*32 .. +32) as 16 f32x2 each (serve all 4 streams) --
    ull w2[4][16];
#pragma unroll
    for (int jj=0;jj<4;jj++){
        const ull* wp = (const ull*)(Whh + (size_t)(j0+jj)*Hsz + kq*32);
#pragma unroll
        for (int i=0;i<16;i++) w2[jj][i] = wp[i];
    }

    // ---- mbar init, cluster-wide visibility, then arm phase 0 of all 8 ----
    const unsigned mb_base = smem_u32(mb);
    if (tid == 0){
#pragma unroll
        for (int i=0;i<8;i++) mbar_init(mb_base + i*8, 1u);
    }
    __syncthreads();
    cluster_arrive(); cluster_wait();        // inits visible before any inbound st.async
    if (tid == 0){
#pragma unroll
        for (int i=0;i<8;i++) mbar_expect(mb_base + i*8, TXB1);
    }
    __syncthreads();

    // ---- DSMEM push addresses: quad rq -> ranks 2rq, 2rq+1 ----
    const unsigned sbase = smem_u32(sh);
    const unsigned rs0 = mapa_rank(sbase,   2*rq);
    const unsigned rs1 = mapa_rank(sbase,   2*rq+1);
    const unsigned rm0 = mapa_rank(mb_base, 2*rq);
    const unsigned rm1 = mapa_rank(mb_base, 2*rq+1);
    // consumer layout within a region: ((k>>5)*CH + (k&31)); our k = j_out
    const unsigned inner = (unsigned)(((j_out>>5)*CH + (j_out&31))*4);

    const float* xwp[4];  float* hsp[4];
#pragma unroll
    for (int s=0;s<4;s++){
        xwp[s] = xw + (size_t)(cl*4+s)*Hsz + j_out;
        hsp[s] = hs + (size_t)(cl*4+s)*Hsz + j_out;
    }

    const bool hi2 = (lane & 2) != 0;
    const bool hi1 = (lane & 1) != 0;

    // per-stream FMA+reduce over region bi
    auto stream_mv = [&](int bi)->float{
        const ull* hq = (const ull*)(sh + bi*HB1 + kq*CH);
        ull a0=0ull, a1=0ull, a2=0ull, a3=0ull;
#pragma unroll
        for (int kk=0;kk<16;kk+=2){
            ulonglong2 p = *(const ulonglong2*)&hq[kk];
            a0 = fma2(p.x, w2[0][kk], a0);  a0 = fma2(p.y, w2[0][kk+1], a0);
            a1 = fma2(p.x, w2[1][kk], a1);  a1 = fma2(p.y, w2[1][kk+1], a1);
            a2 = fma2(p.x, w2[2][kk], a2);  a2 = fma2(p.y, w2[2][kk+1], a2);
            a3 = fma2(p.x, w2[3][kk], a3);  a3 = fma2(p.y, w2[3][kk+1], a3);
        }
        float v[4];
        { float l,h; unpack2(a0,l,h); v[0]=l+h; unpack2(a1,l,h); v[1]=l+h;
          unpack2(a2,l,h); v[2]=l+h; unpack2(a3,l,h); v[3]=l+h; }
        // bits 8,4: pure reduction (output unaffected)
#pragma unroll
        for (int o=0;o<4;o++) v[o] += __shfl_xor_sync(0xffffffffu, v[o], 8);
#pragma unroll
        for (int o=0;o<4;o++) v[o] += __shfl_xor_sync(0xffffffffu, v[o], 4);
        // bit 2 select-fold: v[o] -> output o + (lane&2)
#pragma unroll
        for (int o=0;o<2;o++){
            float keepv = hi2 ? v[o+2] : v[o];
            float sendv = hi2 ? v[o]   : v[o+2];
            v[o] = keepv + __shfl_xor_sync(0xffffffffu, sendv, 2);
        }
        // bit 1 select-fold: v[0] -> output (lane&3) = kq&3
        {
            float keepv = hi1 ? v[1] : v[0];
            float sendv = hi1 ? v[0] : v[1];
            v[0] = keepv + __shfl_xor_sync(0xffffffffu, sendv, 1);
        }
        return v[0];
    };

    auto push_async = [&](float hv, int region){
        unsigned woff = (unsigned)(region*HB1B) + inner;
        unsigned moff = (unsigned)(region*8);
        st_async(rs0 + woff, hv, rm0 + moff);
        st_async(rs1 + woff, hv, rm1 + moff);
    };

    // ---- t = 0 (h_prev = 0) ----
    float xwv[4];
#pragma unroll
    for (int s=0;s<4;s++) xwv[s] = xwp[s][0];
#pragma unroll
    for (int s=0;s<4;s++){
        float hv = ftanh(xwv[s]);
        if (st0) hsp[s][0] = hv;
        push_async(hv, s*2 + 0);             // slot 0
    }
#pragma unroll
    for (int s=0;s<4;s++) xwv[s] = xwp[s][BH];   // prefetch t=1

    for (int t=1;t<Tsz;t++){
        const int m    = (t-1) & 1;                      // slot of h[t-1]
        const unsigned par = (unsigned)(((t-1) >> 1) & 1);
        const int slot = t & 1;                          // slot for h[t]
        const int toff = t << 15;                        // t*BH

#pragma unroll
        for (int s=0;s<4;s++){
            const unsigned mloc = mb_base + (unsigned)((s*2+m)*8);
            mbar_wait(mloc, par);                        // h[t-1] of stream s complete
            if (tid == 0 && t <= 509) mbar_expect(mloc, TXB1);   // re-arm for h[t+1]
            float sum = stream_mv(s*2 + m);
            float hv  = ftanh(sum + xwv[s]);
            if (st0) hsp[s][toff] = hv;
            if (t <= 510) push_async(hv, s*2 + slot);
            if (t != Tsz-1) xwv[s] = xwp[s][toff + BH];  // hides under next segments
            else if (st0)   hlast[(size_t)(cl*4+s)*Hsz + j_out] = hv;
        }
    }
    // no drain needed: t=511 pushed nothing; final waits consumed all inbound tx
}

// ---------------- launch -------------------------------------------------------------
extern "C" void kernel_launch(void* const* d_in, const int* in_sizes, int n_in,
                              void* d_out, int out_size){
    const int*   x    = (const int*)  d_in[0];
    const float* emb  = (const float*)d_in[1];
    const float* Wxh0 = (const float*)d_in[2];
    const float* Whh0 = (const float*)d_in[3];
    const float* bh0  = (const float*)d_in[4];
    const float* Wxh1 = (const float*)d_in[5];
    const float* Whh1 = (const float*)d_in[6];
    const float* bh1  = (const float*)d_in[7];
    const float* Why  = (const float*)d_in[8];
    const float* by   = (const float*)d_in[9];
    float* out = (float*)d_out;

    float *xwbuf, *hs0, *hs1;
    cudaGetSymbolAddress((void**)&xwbuf, g_xw);
    cudaGetSymbolAddress((void**)&hs0,   g_hs0);
    cudaGetSymbolAddress((void**)&hs1,   g_hs1);

    const size_t LOGITS = (size_t)Bsz*Tsz*Vsz;   // 4194304

    dim3 gH(Msz/128, Hsz/128);

    // 1) xw0 = gather(emb, x) @ Wxh0^T + bh0   (gather fused into A-load)
    k_gemm<<<gH, 256>>>(emb, Wxh0, bh0, xwbuf, Msz, Hsz, Esz, 2, x);

    // 2) layer-0 recurrence -> hs0, h_last0
    k_rnn<<<128, 256>>>(xwbuf, hs0, Whh0, out + LOGITS);

    // 3) xw1 = hs0 @ Wxh1^T + bh1
    k_gemm<<<gH, 256>>>(hs0, Wxh1, bh1, xwbuf, Msz, Hsz, Hsz, 0, 0);

    // 4) layer-1 recurrence -> hs1, h_last1
    k_rnn<<<128, 256>>>(xwbuf, hs1, Whh1, out + LOGITS + (size_t)Bsz*Hsz);

    // 5) logits = hs1 @ Why^T + by  (remapped to (b,t,v))
    dim3 gV(Msz/128, Vsz/128);
    k_gemm<<<gV, 256>>>(hs1, Why, by, out, Msz, Vsz, Hsz, 1, 0);
}

// round 12
// speedup vs baseline: 1.2236x; 1.2236x over previous
#include <cuda_runtime.h>
#include <math.h>

typedef unsigned long long ull;

#define Bsz 64
#define Tsz 512
#define Esz 256
#define Hsz 512
#define Vsz 128
#define Msz (Bsz*Tsz)   // 32768 rows

// ---------------- scratch (static device arrays; no runtime allocation) -------------
__device__ float g_xw[Msz*Hsz];     // input projection for current layer (t,b,h)
__device__ float g_hs0[Msz*Hsz];    // layer0 hidden states (t,b,h)
__device__ float g_hs1[Msz*Hsz];    // layer1 hidden states (t,b,h)

// ---------------- f32x2 helpers ------------------------------------------------------
__device__ __forceinline__ ull fma2(ull a, ull b, ull c){
    ull d; asm("fma.rn.f32x2 %0, %1, %2, %3;" : "=l"(d) : "l"(a), "l"(b), "l"(c)); return d;
}
__device__ __forceinline__ ull pack2(float x){
    ull d; asm("mov.b64 %0, {%1, %1};" : "=l"(d) : "f"(x)); return d;
}
__device__ __forceinline__ void unpack2(ull v, float& lo, float& hi){
    asm("mov.b64 {%0, %1}, %2;" : "=f"(lo), "=f"(hi) : "l"(v));
}

// branch-free tanh: 1 - 2/(e^{2x}+1). MUFU-based, ~5 instr, rel err ~3e-7.
__device__ __forceinline__ float ftanh(float x){
    float e = __expf(2.0f*x);
    return 1.0f - __fdividef(2.0f, e + 1.0f);
}

// ---------------- cluster helpers ----------------------------------------------------
__device__ __forceinline__ unsigned smem_u32(const void* p){
    unsigned a;
    asm("{ .reg .u64 t; cvta.to.shared.u64 t, %1; cvt.u32.u64 %0, t; }" : "=r"(a) : "l"(p));
    return a;
}
__device__ __forceinline__ unsigned mapa_rank(unsigned laddr, unsigned r){
    unsigned ra; asm("mapa.shared::cluster.u32 %0, %1, %2;" : "=r"(ra) : "r"(laddr), "r"(r));
    return ra;
}
__device__ __forceinline__ void cluster_arrive(){
    asm volatile("barrier.cluster.arrive.aligned;" ::: "memory");
}
__device__ __forceinline__ void cluster_wait(){
    asm volatile("barrier.cluster.wait.aligned;"   ::: "memory");
}
__device__ __forceinline__ void mbar_init(unsigned addr, unsigned cnt){
    asm volatile("mbarrier.init.shared.b64 [%0], %1;" :: "r"(addr), "r"(cnt) : "memory");
}
// arm: arrive (count 1) + expect tx bytes for the current phase of own mbar
__device__ __forceinline__ void mbar_expect(unsigned addr, unsigned txb){
    asm volatile("mbarrier.arrive.expect_tx.shared.b64 _, [%0], %1;"
                 :: "r"(addr), "r"(txb) : "memory");
}
// self-signaling remote store: data + tx-completion both to the SAME remote CTA
__device__ __forceinline__ void st_async(unsigned raddr, float v, unsigned rmbar){
    asm volatile("st.async.shared::cluster.mbarrier::complete_tx::bytes.u32 [%0], %1, [%2];"
                 :: "r"(raddr), "r"(__float_as_uint(v)), "r"(rmbar) : "memory");
}
// wait own mbar phase with cluster-scope acquire (orders inbound async stores)
__device__ __forceinline__ void mbar_wait(unsigned addr, unsigned parity){
    asm volatile("{\n\t.reg .pred P;\n\t"
        "W_%=:\n\t"
        "mbarrier.try_wait.parity.acquire.cluster.shared::cta.b64 P, [%0], %1, 0x989680;\n\t"
        "@!P bra W_%=;\n\t}\n"
        :: "r"(addr), "r"(parity) : "memory");
}

// ---------------- kernel: double-buffered fp32 GEMM ---------------------------------
// C[M,N] = A[M,K] @ W[N,K]^T + bias
// mode 0: C row-major by A-row.
// mode 1: A-row=(t*B+b) remapped to out[(b*T+t)*N+n] (logits)
// mode 2: A-row gathered through embedding: A[m][k] = emb[x[b*T+t]][k]  (K=Esz)
// Pipeline per 16-wide k-tile: LDG(next tile -> regs) || compute(cur smem buf),
// then STS(next buf), one __syncthreads per tile. Hides ~600cyc LDG latency that
// the R1-R10 version exposed every tile (fma was capped at ~45%).
__global__ void __launch_bounds__(256,2) k_gemm(const float* __restrict__ A,
                                                const float* __restrict__ W,
                                                const float* __restrict__ bias,
                                                float* __restrict__ C,
                                                int M, int N, int K, int mode,
                                                const int* __restrict__ xidx){
    __shared__ __align__(16) float As[2][128*20];   // [m][k], row stride 20 (pad)
    __shared__ __align__(16) float Bs[2][16*130];   // [k][n], row stride 130 (pad)
    const int tid = threadIdx.x;
    const int m0 = blockIdx.x*128;
    const int n0 = blockIdx.y*128;
    const int tx = tid & 15;       // n-group (8 n each)
    const int ty = tid >> 4;       // m-group (8 m each)
    const int mlA = tid >> 2, qA = tid & 3;
    const int nnB = tid & 127, hfB = tid >> 7;
    const int nt = K >> 4;

    // hoisted A/B base pointers (gather index resolved ONCE, not per tile)
    const float* aptr[2];
#pragma unroll
    for (int p=0;p<2;p++){
        int row = m0 + mlA + p*64;
        if (mode == 2){
            int b = row & 63; int tt = row >> 6;
            int v = xidx[b*Tsz + tt];
            aptr[p] = &A[(size_t)v*Esz + qA*4];
        } else {
            aptr[p] = &A[(size_t)row*K + qA*4];
        }
    }
    const float* bptr = &W[(size_t)(n0+nnB)*K + hfB*8];

    ull acc[8][4];
#pragma unroll
    for (int i=0;i<8;i++)
#pragma unroll
        for (int j=0;j<4;j++) acc[i][j] = 0ull;

    float4 ra0, ra1, rb0, rb1;
    // ---- prologue: stage tile 0 ----
    ra0 = *(const float4*)(aptr[0]);
    ra1 = *(const float4*)(aptr[1]);
    rb0 = *(const float4*)(bptr);
    rb1 = *(const float4*)(bptr + 4);
    {
        *(float4*)&As[0][(mlA     )*20 + qA*4] = ra0;
        *(float4*)&As[0][(mlA + 64)*20 + qA*4] = ra1;
        int kb = hfB*8;
        Bs[0][(kb+0)*130+nnB]=rb0.x; Bs[0][(kb+1)*130+nnB]=rb0.y;
        Bs[0][(kb+2)*130+nnB]=rb0.z; Bs[0][(kb+3)*130+nnB]=rb0.w;
        Bs[0][(kb+4)*130+nnB]=rb1.x; Bs[0][(kb+5)*130+nnB]=rb1.y;
        Bs[0][(kb+6)*130+nnB]=rb1.z; Bs[0][(kb+7)*130+nnB]=rb1.w;
    }
    __syncthreads();

    for (int kt=0; kt<nt; kt++){
        const int cur = kt & 1;
        const bool more = (kt+1 < nt);
        if (more){
            int k0 = (kt+1) << 4;
            ra0 = *(const float4*)(aptr[0] + k0);
            ra1 = *(const float4*)(aptr[1] + k0);
            rb0 = *(const float4*)(bptr + k0);
            rb1 = *(const float4*)(bptr + k0 + 4);
        }
        // compute on buffer cur (LDG for next tile in flight)
        const float* Asc = As[cur];
        const float* Bsc = Bs[cur];
#pragma unroll
        for (int kk=0;kk<16;kk++){
            int k = (kk + tx) & 15;                 // per-lane k rotation: kills bank conflicts
            const ull* bp = (const ull*)&Bsc[k*130 + tx*8];
            ull b0=bp[0], b1=bp[1], b2v=bp[2], b3=bp[3];
#pragma unroll
            for (int i=0;i<8;i++){
                ull a2 = pack2(Asc[(ty*8+i)*20 + k]);
                acc[i][0] = fma2(a2, b0,  acc[i][0]);
                acc[i][1] = fma2(a2, b1,  acc[i][1]);
                acc[i][2] = fma2(a2, b2v, acc[i][2]);
                acc[i][3] = fma2(a2, b3,  acc[i][3]);
            }
        }
        if (more){
            const int nxt = cur ^ 1;
            *(float4*)&As[nxt][(mlA     )*20 + qA*4] = ra0;
            *(float4*)&As[nxt][(mlA + 64)*20 + qA*4] = ra1;
            int kb = hfB*8;
            Bs[nxt][(kb+0)*130+nnB]=rb0.x; Bs[nxt][(kb+1)*130+nnB]=rb0.y;
            Bs[nxt][(kb+2)*130+nnB]=rb0.z; Bs[nxt][(kb+3)*130+nnB]=rb0.w;
            Bs[nxt][(kb+4)*130+nnB]=rb1.x; Bs[nxt][(kb+5)*130+nnB]=rb1.y;
            Bs[nxt][(kb+6)*130+nnB]=rb1.z; Bs[nxt][(kb+7)*130+nnB]=rb1.w;
            __syncthreads();
        }
    }
    // epilogue: + bias, write (with optional logits remap)
#pragma unroll
    for (int i=0;i<8;i++){
        int row = m0 + ty*8 + i;
        size_t obase;
        if (mode == 1){ int b = row & 63; int tt = row >> 6; obase = ((size_t)b*Tsz + tt)*(size_t)N; }
        else obase = (size_t)row * (size_t)N;
#pragma unroll
        for (int jn=0;jn<4;jn++){
            int n = n0 + tx*8 + jn*2;
            float2 bv = *(const float2*)&bias[n];
            float lo, hi; unpack2(acc[i][jn], lo, hi);
            float2 o; o.x = lo + bv.x; o.y = hi + bv.y;
            *(float2*)&C[obase + n] = o;
        }
    }
}

// ---------------- kernel: two-stream st.async recurrence (R10 champion, verbatim) ----
// 128 CTAs = 16 clusters x 8 CTAs, 256 thr. Cluster cl owns batches [cl*4, cl*4+4):
// stream A = {+0,+1}, stream B = {+2,+3} (independent chains, SAME weight regs).
// Sync: per-(stream,slot) tx-counting mbarrier. Producers push each output via
// st.async (data + complete_tx to the same remote CTA) -- self-ordering, NO fences,
// NO cluster barrier in the loop. Consumer: tid0 arms expect_tx(4096)/phase; all
// threads try_wait parity. Ping-pong mbars/buffers make the <=1-step producer lead
// race-free. Stream A's DSMEM flight overlaps stream B's compute and vice versa.
#define CH   36                    // 32 floats + 4 pad per k-slice
#define HB   (2*16*CH)             // 2 batches x 16 slices = 1152 floats per region
#define HB4  (HB*4)                // bytes per region
#define TXB  4096u                 // inbound bytes per mbar phase: 1024 floats

__global__ void __launch_bounds__(256,1) __cluster_dims__(8,1,1)
k_rnn(const float* __restrict__ xw, float* __restrict__ hs,
      const float* __restrict__ Whh, float* __restrict__ hlast){
    __shared__ __align__(16) float sh[4*HB];             // region = stream*2 + slot
    __shared__ __align__(8) ull mb[4];                   // mbar per region
    const int cl   = blockIdx.x >> 3;
    const int rank = blockIdx.x & 7;
    const int tid  = threadIdx.x;
    const int w    = tid >> 5;
    const int lane = tid & 31;
    const int jq   = lane >> 4;
    const int kq   = lane & 15;
    const int j0   = rank*64 + w*8 + jq*4;
    const int bw   = (kq >> 3) & 1;          // batch within stream
    const int j_out= j0 + ((kq >> 1) & 3);
    const int odd  = kq & 1;
    const int bA   = cl*4 + bw;              // absolute batch, stream A output
    const int bB   = cl*4 + 2 + bw;          // absolute batch, stream B output
    const int BH   = Bsz*Hsz;

    // ---- weights: W_hh[j0+jj][kq*32 .. +32) as 16 f32x2 each (serve both streams) ----
    ull w2[4][16];
#pragma unroll
    for (int jj=0;jj<4;jj++){
        const ull* wp = (const ull*)(Whh + (size_t)(j0+jj)*Hsz + kq*32);
#pragma unroll
        for (int i=0;i<16;i++) w2[jj][i] = wp[i];
    }

    // ---- mbar init, cluster-wide visibility, then arm phase 0 of all 4 ----
    const unsigned mb_base = smem_u32(mb);
    if (tid == 0){
#pragma unroll
        for (int i=0;i<4;i++) mbar_init(mb_base + i*8, 1u);
    }
    __syncthreads();
    cluster_arrive(); cluster_wait();        // inits visible before any inbound st.async
    if (tid == 0){
#pragma unroll
        for (int i=0;i<4;i++) mbar_expect(mb_base + i*8, TXB);
    }

    // ---- DSMEM push addresses (data + mbar, SAME 4 ranks) ----
    const unsigned sbase = smem_u32(sh);
    unsigned rsh[4], rmb[4];
#pragma unroll
    for (int r=0;r<4;r++){
        rsh[r] = mapa_rank(sbase,   odd*4 + r);
        rmb[r] = mapa_rank(mb_base, odd*4 + r);
    }
    // consumer layout within a region: ((b*16 + (k>>5))*CH + (k&31)); our k = j_out
    const unsigned inner = (unsigned)(((bw*16 + (j_out>>5))*CH + (j_out&31))*4);

    const float* xwpA = xw + (size_t)bA*Hsz + j_out;
    const float* xwpB = xw + (size_t)bB*Hsz + j_out;
    float*       hspA = hs + (size_t)bA*Hsz + j_out;
    float*       hspB = hs + (size_t)bB*Hsz + j_out;

    const bool hi8 = (lane & 8) != 0;
    const bool hi4 = (lane & 4) != 0;
    const bool hi2 = (lane & 2) != 0;

    // per-stream FMA+reduce over region bi (verified in R7/R10)
    auto stream_mv = [&](int bi)->float{
        const float* buf = sh + bi*HB;
        ull acc[2][4];
#pragma unroll
        for (int b=0;b<2;b++)
#pragma unroll
            for (int jj=0;jj<4;jj++) acc[b][jj] = 0ull;
#pragma unroll
        for (int b=0;b<2;b++){
            const ull* hq = (const ull*)(buf + (b*16 + kq)*CH);
#pragma unroll
            for (int kk=0;kk<16;kk+=2){
                ulonglong2 p = *(const ulonglong2*)&hq[kk];
#pragma unroll
                for (int jj=0;jj<4;jj++){
                    acc[b][jj] = fma2(p.x, w2[jj][kk],   acc[b][jj]);
                    acc[b][jj] = fma2(p.y, w2[jj][kk+1], acc[b][jj]);
                }
            }
        }
        float v[8];
#pragma unroll
        for (int b=0;b<2;b++)
#pragma unroll
            for (int jj=0;jj<4;jj++){
                float l, h; unpack2(acc[b][jj], l, h);
                v[b*4+jj] = l + h;
            }
#pragma unroll
        for (int o=0;o<4;o++){
            float keepv = hi8 ? v[o+4] : v[o];
            float sendv = hi8 ? v[o]   : v[o+4];
            v[o] = keepv + __shfl_xor_sync(0xffffffffu, sendv, 8);
        }
#pragma unroll
        for (int o=0;o<2;o++){
            float keepv = hi4 ? v[o+2] : v[o];
            float sendv = hi4 ? v[o]   : v[o+2];
            v[o] = keepv + __shfl_xor_sync(0xffffffffu, sendv, 4);
        }
        {
            float keepv = hi2 ? v[1] : v[0];
            float sendv = hi2 ? v[0] : v[1];
            v[0] = keepv + __shfl_xor_sync(0xffffffffu, sendv, 2);
        }
        v[0] += __shfl_xor_sync(0xffffffffu, v[0], 1);
        return v[0];
    };

    // push one output to 4 ranks, each store self-signals that rank's region mbar
    auto push_async = [&](float hv, int region){
        unsigned woff = (unsigned)(region*HB4) + inner;
        unsigned moff = (unsigned)(region*8);
#pragma unroll
        for (int r=0;r<4;r++) st_async(rsh[r] + woff, hv, rmb[r] + moff);
    };

    // ---- t = 0 (h_prev = 0) ----
    float xwA = xwpA[0], xwB = xwpB[0];
    {
        float hvA = ftanh(xwA);
        if (!odd) hspA[0] = hvA;
        push_async(hvA, 0);                  // stream A, slot 0
        float hvB = ftanh(xwB);
        if (odd) hspB[0] = hvB;
        push_async(hvB, 2);                  // stream B, slot 0
    }
    xwA = xwpA[BH];  xwB = xwpB[BH];         // prefetch t=1

    for (int t=1;t<Tsz;t++){
        const int m   = (t-1) & 1;                       // mbar/buffer slot of h[t-1]
        const unsigned par = (unsigned)(((t-1) >> 1) & 1);
        const int slot = t & 1;                          // slot for h[t]
        const int toff = t << 15;                        // t*BH

        // ---------- stream A ----------
        mbar_wait(mb_base + (0*2+m)*8, par);             // h[t-1] of A complete
        if (tid == 0 && t <= 509) mbar_expect(mb_base + (0*2+m)*8, TXB);  // arm h[t+1]
        float sumA = stream_mv(0*2 + m);
        float hvA = ftanh(sumA + xwA);
        if (!odd) hspA[toff] = hvA;
        if (t <= 510) push_async(hvA, 0*2 + slot);
        if (t != Tsz-1) xwA = xwpA[toff + BH];           // hides under B segment
        else if (!odd)  hlast[bA*Hsz + j_out] = hvA;

        // ---------- stream B ----------
        mbar_wait(mb_base + (1*2+m)*8, par);             // h[t-1] of B complete
        if (tid == 0 && t <= 509) mbar_expect(mb_base + (1*2+m)*8, TXB);
        float sumB = stream_mv(1*2 + m);
        float hvB = ftanh(sumB + xwB);
        if (odd) hspB[toff] = hvB;
        if (t <= 510) push_async(hvB, 1*2 + slot);
        if (t != Tsz-1) xwB = xwpB[toff + BH];
        else if (odd)   hlast[bB*Hsz + j_out] = hvB;
    }
    // no drain needed: t=511 pushed nothing; final waits consumed all inbound tx
}

// ---------------- launch -------------------------------------------------------------
extern "C" void kernel_launch(void* const* d_in, const int* in_sizes, int n_in,
                              void* d_out, int out_size){
    const int*   x    = (const int*)  d_in[0];
    const float* emb  = (const float*)d_in[1];
    const float* Wxh0 = (const float*)d_in[2];
    const float* Whh0 = (const float*)d_in[3];
    const float* bh0  = (const float*)d_in[4];
    const float* Wxh1 = (const float*)d_in[5];
    const float* Whh1 = (const float*)d_in[6];
    const float* bh1  = (const float*)d_in[7];
    const float* Why  = (const float*)d_in[8];
    const float* by   = (const float*)d_in[9];
    float* out = (float*)d_out;

    float *xwbuf, *hs0, *hs1;
    cudaGetSymbolAddress((void**)&xwbuf, g_xw);
    cudaGetSymbolAddress((void**)&hs0,   g_hs0);
    cudaGetSymbolAddress((void**)&hs1,   g_hs1);

    const size_t LOGITS = (size_t)Bsz*Tsz*Vsz;   // 4194304

    dim3 gH(Msz/128, Hsz/128);

    // 1) xw0 = gather(emb, x) @ Wxh0^T + bh0   (gather fused into A-load)
    k_gemm<<<gH, 256>>>(emb, Wxh0, bh0, xwbuf, Msz, Hsz, Esz, 2, x);

    // 2) layer-0 recurrence -> hs0, h_last0
    k_rnn<<<128, 256>>>(xwbuf, hs0, Whh0, out + LOGITS);

    // 3) xw1 = hs0 @ Wxh1^T + bh1
    k_gemm<<<gH, 256>>>(hs0, Wxh1, bh1, xwbuf, Msz, Hsz, Hsz, 0, 0);

    // 4) layer-1 recurrence -> hs1, h_last1
    k_rnn<<<128, 256>>>(xwbuf, hs1, Whh1, out + LOGITS + (size_t)Bsz*Hsz);

    // 5) logits = hs1 @ Why^T + by  (remapped to (b,t,v))
    dim3 gV(Msz/128, Vsz/128);
    k_gemm<<<gV, 256>>>(hs1, Why, by, out, Msz, Vsz, Hsz, 1, 0);
}